// round 11
// baseline (speedup 1.0000x reference)
#include <cuda_runtime.h>
#include <cstdint>

#define NF    33        // feature_dim + flag
#define BOND  64
#define CLU   8         // CTAs per cluster
#define ISL   8         // i-rows of core per CTA
#define NBC   8         // batches per cluster
#define TLEN  512
#define NTH   256
#define OUTD  32

typedef unsigned long long u64;

// ---- shared memory layout (bytes) ----
#define CORE_OFF 0
#define CORE_SZ  (ISL * NF * BOND * 4)        // 67584
#define U_OFF    (CORE_OFF + CORE_SZ)         // 67584
#define U_SZ     (ISL * NF * 4 * 8)           // 8448  (1056 u64 b-pairs)
#define P_OFF    (U_OFF + U_SZ)               // 76032
#define P_SZ     (256 * 9 * 8)                // 18432 (swizzled partials, stride 9)
#define V_OFF    (P_OFF + P_SZ)               // 94464
#define V_SZ     512                          // 8 rows x 4 bp, stride 5 u64
#define MAIL_OFF (V_OFF + V_SZ)               // 94976
#define MAIL_SZ  (2 * CLU * 32 * 8)           // 4096  (double-buffered scatter mailbox)
#define X_OFF    (MAIL_OFF + MAIL_SZ)         // 99072
#define X_SZ     (2 * NF * NBC * 4)           // 2112
#define SMEM_TOTAL (X_OFF + X_SZ)             // 101184  -> 2 CTAs/SM

// ---- f32x2 packed math ----
__device__ __forceinline__ u64 pack2(float v) {
    u64 r; asm("mov.b64 %0, {%1, %1};" : "=l"(r) : "f"(v)); return r;
}
__device__ __forceinline__ void fma2(u64& d, u64 a, u64 b) {
    asm("fma.rn.f32x2 %0, %1, %2, %0;" : "+l"(d) : "l"(a), "l"(b));
}
__device__ __forceinline__ u64 mul2(u64 a, u64 b) {
    u64 r; asm("mul.rn.f32x2 %0, %1, %2;" : "=l"(r) : "l"(a), "l"(b)); return r;
}
__device__ __forceinline__ void add2(u64& d, u64 a) {
    asm("add.rn.f32x2 %0, %0, %1;" : "+l"(d) : "l"(a));
}

__device__ __forceinline__ void cp_async4(uint32_t smem_addr, const void* gptr) {
    asm volatile("cp.async.ca.shared.global [%0], [%1], 4;\n" :: "r"(smem_addr), "l"(gptr));
}
__device__ __forceinline__ void cp_async_commit() {
    asm volatile("cp.async.commit_group;\n" ::: "memory");
}
__device__ __forceinline__ void cp_async_wait0() {
    asm volatile("cp.async.wait_group 0;\n" ::: "memory");
}

__device__ __forceinline__ void st_cluster_u64(uint32_t laddr, int dst_rank, u64 v) {
    uint32_t raddr;
    asm volatile("mapa.shared::cluster.u32 %0, %1, %2;" : "=r"(raddr) : "r"(laddr), "r"(dst_rank));
    asm volatile("st.shared::cluster.b64 [%0], %1;" :: "r"(raddr), "l"(v) : "memory");
}
__device__ __forceinline__ void cluster_barrier() {
    asm volatile("barrier.cluster.arrive.aligned;" ::: "memory");
    asm volatile("barrier.cluster.wait.aligned;" ::: "memory");
}

__global__ __launch_bounds__(NTH, 2) __cluster_dims__(CLU, 1, 1)
void umps_c8_kernel(const float* __restrict__ x,      // (256, 512, 33)
                    const float* __restrict__ core,   // (64, 33, 64)
                    const float* __restrict__ alpha,  // (64)
                    const float* __restrict__ outc,   // (64, 32)
                    float*       __restrict__ out)    // (256, 32)
{
    extern __shared__ char smem[];
    float* sCore = (float*)(smem + CORE_OFF);   // [8 iL][33 f][64 j]
    u64*   sU    = (u64*)  (smem + U_OFF);      // [(iL*33+f)*4 + bp]
    u64*   sP    = (u64*)  (smem + P_OFF);      // [idx*9 + g]
    u64*   sVu   = (u64*)  (smem + V_OFF);      // [iL*5 + bp]   (this CTA's 8 rows)
    u64*   sMail = (u64*)  (smem + MAIL_OFF);   // [(buf*8 + srcrank)*32 + pos]
    float* sX    = (float*)(smem + X_OFF);      // [buf][33 f][8 b]

    const int tid  = threadIdx.x;
    const int rank = blockIdx.x & 7;
    const int b0   = (blockIdx.x >> 3) * NBC;   // cluster batch base
    const int g    = tid >> 5;                  // warp id = local i-row 0..7
    const int l    = tid & 31;
    const int jv   = l >> 1;                    // j-quad 0..15
    const int bph  = l & 1;                     // batch-pair half 0..1
    const uint32_t smem_u32 = (uint32_t)__cvta_generic_to_shared(smem);

    // ---- load this rank's 8-row core slice (fp32, exact) ----
    {
        const float4* src = (const float4*)(core + (size_t)(rank * ISL) * NF * BOND);
        float4* dst = (float4*)sCore;
        for (int p = tid; p < ISL * NF * BOND / 4; p += NTH) dst[p] = src[p];
    }

    // ---- init this CTA's V rows: V[iL][b] = alpha[rank*8 + iL] ----
    if (tid < 32) {
        int iL = tid >> 2, bp = tid & 3;
        sVu[iL * 5 + bp] = pack2(alpha[rank * ISL + iL]);
    }

    // ---- preload X(t=0): layout [f][8 b] ----
    for (int p = tid; p < NF * NBC; p += NTH) {
        int f = p >> 3, bl = p & 7;
        cp_async4(smem_u32 + X_OFF + (uint32_t)(p * 4),
                  x + ((size_t)(b0 + bl) * TLEN + 0) * NF + f);
    }
    cp_async_commit();

    for (int t = 0; t < TLEN; ++t) {
        cp_async_wait0();
        __syncthreads();                          // B0: X(t) landed, sVu(t) visible

        const int buf = t & 1;

        // ---- build U: U[iL][f][bp] = V[iL][bp] * X[f][bp]  (1056 u64) ----
        {
            const u64* sXu = (const u64*)(sX + buf * (NF * NBC));
            for (int p = tid; p < ISL * NF * 4; p += NTH) {
                int iL = p / 132, r2 = p - iL * 132;
                int f = r2 >> 2, bp = r2 & 3;
                sU[p] = mul2(sVu[iL * 5 + bp], sXu[f * 4 + bp]);
            }
        }

        // ---- prefetch X(t+1) ----
        if (t + 1 < TLEN) {
            for (int p = tid; p < NF * NBC; p += NTH) {
                int f = p >> 3, bl = p & 7;
                cp_async4(smem_u32 + X_OFF + (uint32_t)((((t + 1) & 1) * NF * NBC + p) * 4),
                          x + ((size_t)(b0 + bl) * TLEN + (t + 1)) * NF + f);
            }
        }
        cp_async_commit();
        __syncthreads();                          // B1: U visible

        // ---- GEMM: warp g owns i-row g; thread: 4 j (jv) x 4 b (bph pair-pair) ----
        u64 acc[8];
        #pragma unroll
        for (int q = 0; q < 8; ++q) acc[q] = 0ull;

        const float4*     Crow = (const float4*)sCore + (size_t)g * (NF * 16) + jv;
        const ulonglong2* Urow = (const ulonglong2*)sU + (size_t)g * (NF * 2) + bph;

        #pragma unroll 11
        for (int f = 0; f < NF; ++f) {
            float4     c4 = Crow[f * 16];         // core[g][f][jv*4..+3]
            ulonglong2 uu = Urow[f * 2];          // U[g][f][bph*2], [.. +1]
            u64 u0 = uu.x, u1 = uu.y;
            u64 cc;
            cc = pack2(c4.x); fma2(acc[0], u0, cc); fma2(acc[1], u1, cc);
            cc = pack2(c4.y); fma2(acc[2], u0, cc); fma2(acc[3], u1, cc);
            cc = pack2(c4.z); fma2(acc[4], u0, cc); fma2(acc[5], u1, cc);
            cc = pack2(c4.w); fma2(acc[6], u0, cc); fma2(acc[7], u1, cc);
        }

        // ---- store partials, swizzled: col c = (jv*4+jj)*4 + bph*2+pp,
        //      idx = (c&15)*16 + (c>>4) = (jj*4+bph*2+pp)*16 + jv ----
        #pragma unroll
        for (int jj = 0; jj < 4; ++jj)
            #pragma unroll
            for (int pp = 0; pp < 2; ++pp)
                sP[((jj * 4 + bph * 2 + pp) * 16 + jv) * 9 + g] = acc[jj * 2 + pp];
        __syncthreads();                          // B2: partials visible

        // ---- reduce 8 i-rows; scatter to owner rank's mailbox ----
        {
            u64 s = sP[tid * 9 + 0];              // thread tid handles idx = tid
            #pragma unroll
            for (int gg = 1; gg < ISL; ++gg) add2(s, sP[tid * 9 + gg]);
            // col c = (tid&15)*16 + (tid>>4); owner q = c>>5; pos = c&31
            int q   = (tid & 15) >> 1;
            int pos = (tid & 1) * 16 + (tid >> 4);
            st_cluster_u64(smem_u32 + MAIL_OFF +
                           (uint32_t)(((buf * CLU + rank) * 32 + pos) * 8), q, s);
        }

        cluster_barrier();                        // all scatters visible

        // ---- owner-side: sum 8 rank-partials for this CTA's own 32 cols ----
        if (tid < 32) {
            const u64* mb = sMail + buf * (CLU * 32);
            u64 v = mb[tid];
            #pragma unroll
            for (int r = 1; r < CLU; ++r) add2(v, mb[r * 32 + tid]);
            // col c = rank*32 + tid -> j = rank*8 + (tid>>2), bp = tid&3
            sVu[(tid >> 2) * 5 + (tid & 3)] = v;  // becomes next step's V row
        }
        // sVu visibility for next step via loop-top B0
    }

    // ---- gather final V rows to rank 0 (mail buf0 region is free) ----
    if (tid < 32) {
        u64 v = sVu[(tid >> 2) * 5 + (tid & 3)];
        st_cluster_u64(smem_u32 + MAIL_OFF + (uint32_t)((rank * 32 + tid) * 8), 0, v);
    }
    cluster_barrier();

    // ---- epilogue on rank 0: out[b][o] = sum_i V[i][b] * outc[i][o] ----
    if (rank == 0) {
        const float* Vf = (const float*)sMail;   // u64 slot (i>>3)*32 + (i&7)*4 + (b>>1)
        int b = tid >> 5, o = tid & 31;
        float s = 0.f;
        #pragma unroll 8
        for (int i = 0; i < BOND; ++i) {
            float v = Vf[(((i >> 3) * 32 + (i & 7) * 4 + (b >> 1)) << 1) + (b & 1)];
            s = fmaf(v, __ldg(outc + i * OUTD + o), s);
        }
        out[(size_t)(b0 + b) * OUTD + o] = s;
    }
}

extern "C" void kernel_launch(void* const* d_in, const int* in_sizes, int n_in,
                              void* d_out, int out_size) {
    const float* x     = (const float*)d_in[0];   // (256,512,33) fp32
    const float* core  = (const float*)d_in[1];   // (64,33,64)  fp32
    const float* alpha = (const float*)d_in[2];   // (64)        fp32
    const float* outc  = (const float*)d_in[3];   // (64,32)     fp32
    float* out = (float*)d_out;                   // (256,32)    fp32

    cudaFuncSetAttribute(umps_c8_kernel,
                         cudaFuncAttributeMaxDynamicSharedMemorySize, SMEM_TOTAL);
    // 32 clusters x 8 CTAs = 256 CTAs, ~2 CTAs/SM (101 KB smem each)
    umps_c8_kernel<<<256, NTH, SMEM_TOTAL>>>(x, core, alpha, outc, out);
}

// round 12
// speedup vs baseline: 1.1183x; 1.1183x over previous
#include <cuda_runtime.h>
#include <cstdint>

#define NF    33        // feature_dim + flag
#define BOND  64
#define CLU   8         // CTAs per cluster
#define ISL   8         // i-rows of core per CTA (one per warp)
#define NBC   8         // batches per cluster
#define TLEN  512
#define NTH   256
#define OUTD  32

typedef unsigned long long u64;

// ---- f32x2 packed math ----
__device__ __forceinline__ u64 pack2(float v) {
    u64 r; asm("mov.b64 %0, {%1, %1};" : "=l"(r) : "f"(v)); return r;
}
__device__ __forceinline__ void fma2(u64& d, u64 a, u64 b) {
    asm("fma.rn.f32x2 %0, %1, %2, %0;" : "+l"(d) : "l"(a), "l"(b));
}
__device__ __forceinline__ u64 mul2(u64 a, u64 b) {
    u64 r; asm("mul.rn.f32x2 %0, %1, %2;" : "=l"(r) : "l"(a), "l"(b)); return r;
}
__device__ __forceinline__ void add2(u64& d, u64 a) {
    asm("add.rn.f32x2 %0, %0, %1;" : "+l"(d) : "l"(a));
}

__device__ __forceinline__ void cp_async4(uint32_t smem_addr, const void* gptr) {
    asm volatile("cp.async.ca.shared.global [%0], [%1], 4;\n" :: "r"(smem_addr), "l"(gptr));
}
__device__ __forceinline__ void cp_async_commit() {
    asm volatile("cp.async.commit_group;\n" ::: "memory");
}
__device__ __forceinline__ void cp_async_wait0() {
    asm volatile("cp.async.wait_group 0;\n" ::: "memory");
}

__device__ __forceinline__ void st_cluster_u64(uint32_t laddr, int dst_rank, u64 v) {
    uint32_t raddr;
    asm volatile("mapa.shared::cluster.u32 %0, %1, %2;" : "=r"(raddr) : "r"(laddr), "r"(dst_rank));
    asm volatile("st.shared::cluster.b64 [%0], %1;" :: "r"(raddr), "l"(v) : "memory");
}
__device__ __forceinline__ void cluster_barrier() {
    asm volatile("barrier.cluster.arrive.aligned;" ::: "memory");
    asm volatile("barrier.cluster.wait.aligned;" ::: "memory");
}

__global__ __launch_bounds__(NTH, 2) __cluster_dims__(CLU, 1, 1)
void umps_rcore_kernel(const float* __restrict__ x,      // (256, 512, 33)
                       const float* __restrict__ core,   // (64, 33, 64)
                       const float* __restrict__ alpha,  // (64)
                       const float* __restrict__ outc,   // (64, 32)
                       float*       __restrict__ out)    // (256, 32)
{
    __shared__ u64   sU[ISL * 132];      // [iL*132 + f*4 + bp]   8448 B (warp-private rows)
    __shared__ u64   sP[256 * 9];        // [sc*9 + g] swizzled  18432 B
    __shared__ u64   sVu[40];            // [iL*5 + bp]            320 B (this CTA's 8 rows)
    __shared__ u64   sMail[2 * CLU * 32];// [(buf*8+src)*32+pos]  4096 B
    __shared__ float sX[2 * NF * NBC];   // [buf][f][8 b]         2112 B

    const int tid  = threadIdx.x;
    const int rank = blockIdx.x & 7;
    const int b0   = (blockIdx.x >> 3) * NBC;   // cluster batch base
    const int g    = tid >> 5;                  // warp = local i-row 0..7
    const int l    = tid & 31;                  // lane = j-pair index (j = 2l, 2l+1)
    const uint32_t sx_base   = (uint32_t)__cvta_generic_to_shared(&sX[0]);
    const uint32_t mail_base = (uint32_t)__cvta_generic_to_shared(&sMail[0]);

    // ---- core slice -> REGISTERS: cR[f] = core[rank*8+g][f][2l .. 2l+1] ----
    float2 cR[NF];
    {
        const float* cg = core + ((size_t)(rank * ISL + g) * NF) * BOND + 2 * l;
        #pragma unroll
        for (int f = 0; f < NF; ++f) cR[f] = *(const float2*)(cg + f * BOND);
    }

    // ---- init this CTA's V rows: V[iL][b] = alpha[rank*8 + iL] ----
    if (tid < 32) sVu[(tid >> 2) * 5 + (tid & 3)] = pack2(alpha[rank * ISL + (tid >> 2)]);

    // ---- preload X(t=0): layout [f][8 b] ----
    for (int p = tid; p < NF * NBC; p += NTH) {
        int f = p >> 3, bl = p & 7;
        cp_async4(sx_base + (uint32_t)(p * 4),
                  x + ((size_t)(b0 + bl) * TLEN + 0) * NF + f);
    }
    cp_async_commit();

    for (int t = 0; t < TLEN; ++t) {
        cp_async_wait0();
        __syncthreads();                          // B0: X(t) landed, sVu(t) visible

        const int buf = t & 1;

        // ---- prefetch X(t+1) early (fills buf^1) ----
        if (t + 1 < TLEN) {
            for (int p = tid; p < NF * NBC; p += NTH) {
                int f = p >> 3, bl = p & 7;
                cp_async4(sx_base + (uint32_t)(((buf ^ 1) * NF * NBC + p) * 4),
                          x + ((size_t)(b0 + bl) * TLEN + (t + 1)) * NF + f);
            }
        }
        cp_async_commit();

        // ---- U-build (warp-private): U[g][f][bp] = V[g][bp] * X[f][bp] ----
        {
            const u64* sXu = (const u64*)(sX + buf * (NF * NBC));
            u64 vb0 = sVu[g * 5 + 0], vb1 = sVu[g * 5 + 1];
            u64 vb2 = sVu[g * 5 + 2], vb3 = sVu[g * 5 + 3];
            u64* Uw = sU + g * 132;
            #pragma unroll
            for (int k = 0; k < 4; ++k) {
                int r = l + 32 * k;
                u64 vv = (r & 2) ? ((r & 1) ? vb3 : vb2) : ((r & 1) ? vb1 : vb0);
                Uw[r] = mul2(vv, sXu[r]);
            }
            if (l < 4) {
                int r = l + 128;
                u64 vv = (l & 2) ? ((l & 1) ? vb3 : vb2) : ((l & 1) ? vb1 : vb0);
                Uw[r] = mul2(vv, sXu[r]);
            }
            __syncwarp();
        }

        // ---- GEMM: acc[jj*4+bp], j = 2l+jj, core from registers ----
        u64 acc[8];
        #pragma unroll
        for (int q = 0; q < 8; ++q) acc[q] = 0ull;

        const ulonglong2* Ur = (const ulonglong2*)(sU + g * 132);
        #pragma unroll
        for (int f = 0; f < NF; ++f) {
            ulonglong2 ua = Ur[2 * f];            // bp 0,1 (warp-broadcast)
            ulonglong2 ub = Ur[2 * f + 1];        // bp 2,3
            u64 c0 = pack2(cR[f].x);
            u64 c1 = pack2(cR[f].y);
            fma2(acc[0], ua.x, c0); fma2(acc[1], ua.y, c0);
            fma2(acc[2], ub.x, c0); fma2(acc[3], ub.y, c0);
            fma2(acc[4], ua.x, c1); fma2(acc[5], ua.y, c1);
            fma2(acc[6], ub.x, c1); fma2(acc[7], ub.y, c1);
        }

        // ---- store partials, conflict-free swizzle sc = q*32 + l ----
        #pragma unroll
        for (int q = 0; q < 8; ++q)
            sP[(q * 32 + l) * 9 + g] = acc[q];
        __syncthreads();                          // B2: partials visible

        // ---- reduce 8 i-rows; scatter to owner rank's mailbox ----
        {
            u64 s = sP[tid * 9];
            #pragma unroll
            for (int gg = 1; gg < ISL; ++gg) add2(s, sP[tid * 9 + gg]);
            int jp = tid & 31, q = tid >> 5;
            int jj = q >> 2, bp = q & 3;
            int j  = 2 * jp + jj;
            int own = j >> 3;
            int pos = (j & 7) * 4 + bp;
            st_cluster_u64(mail_base + (uint32_t)(((buf * CLU + rank) * 32 + pos) * 8), own, s);
        }

        cluster_barrier();                        // all scatters visible

        // ---- owner-side: sum 8 rank-partials -> this CTA's V rows ----
        if (tid < 32) {
            const u64* mb = sMail + buf * (CLU * 32);
            u64 v = mb[tid];
            #pragma unroll
            for (int r = 1; r < CLU; ++r) add2(v, mb[r * 32 + tid]);
            sVu[(tid >> 2) * 5 + (tid & 3)] = v;
        }
        // sVu visibility for next step via loop-top B0
    }

    // ---- gather final V rows to rank 0 (mail buf0 region is free) ----
    if (tid < 32) {
        u64 v = sVu[(tid >> 2) * 5 + (tid & 3)];
        st_cluster_u64(mail_base + (uint32_t)((rank * 32 + tid) * 8), 0, v);
    }
    cluster_barrier();

    // ---- epilogue on rank 0: out[b][o] = sum_i V[i][b] * outc[i][o] ----
    if (rank == 0) {
        const float* Vf = (const float*)sMail;   // u64 slot (i>>3)*32 + (i&7)*4 + (b>>1)
        int b = tid >> 5, o = tid & 31;
        float s = 0.f;
        #pragma unroll 8
        for (int i = 0; i < BOND; ++i) {
            float v = Vf[(((i >> 3) * 32 + (i & 7) * 4 + (b >> 1)) << 1) + (b & 1)];
            s = fmaf(v, __ldg(outc + i * OUTD + o), s);
        }
        out[(size_t)(b0 + b) * OUTD + o] = s;
    }
}

extern "C" void kernel_launch(void* const* d_in, const int* in_sizes, int n_in,
                              void* d_out, int out_size) {
    const float* x     = (const float*)d_in[0];   // (256,512,33) fp32
    const float* core  = (const float*)d_in[1];   // (64,33,64)  fp32
    const float* alpha = (const float*)d_in[2];   // (64)        fp32
    const float* outc  = (const float*)d_in[3];   // (64,32)     fp32
    float* out = (float*)d_out;                   // (256,32)    fp32

    // 32 clusters x 8 CTAs = 256 CTAs, 2 CTAs/SM (smem ~33 KB, regs ~110)
    umps_rcore_kernel<<<256, NTH>>>(x, core, alpha, outc, out);
}

// round 15
// speedup vs baseline: 1.1853x; 1.0599x over previous
#include <cuda_runtime.h>
#include <cstdint>

#define NFX   32        // features f = 1..32 (f=0 is the exact identity flag slice)
#define BOND  64
#define CLU   8         // CTAs per cluster
#define ISL   8         // i-rows per CTA (one per warp)
#define NBC   8         // batches per cluster
#define TLEN  512
#define NTH   256
#define OUTD  32

typedef unsigned long long u64;

// ---- f32x2 packed math ----
__device__ __forceinline__ u64 pack2(float v) {
    u64 r; asm("mov.b64 %0, {%1, %1};" : "=l"(r) : "f"(v)); return r;
}
__device__ __forceinline__ void fma2(u64& d, u64 a, u64 b) {
    asm("fma.rn.f32x2 %0, %1, %2, %0;" : "+l"(d) : "l"(a), "l"(b));
}
__device__ __forceinline__ u64 mul2(u64 a, u64 b) {
    u64 r; asm("mul.rn.f32x2 %0, %1, %2;" : "=l"(r) : "l"(a), "l"(b)); return r;
}
__device__ __forceinline__ void add2(u64& d, u64 a) {
    asm("add.rn.f32x2 %0, %0, %1;" : "+l"(d) : "l"(a));
}

__device__ __forceinline__ void cp_async4(uint32_t smem_addr, const void* gptr) {
    asm volatile("cp.async.ca.shared.global [%0], [%1], 4;\n" :: "r"(smem_addr), "l"(gptr));
}
__device__ __forceinline__ void cp_async_commit() {
    asm volatile("cp.async.commit_group;\n" ::: "memory");
}
__device__ __forceinline__ void cp_async_wait0() {
    asm volatile("cp.async.wait_group 0;\n" ::: "memory");
}

__device__ __forceinline__ void st_cluster_u64(uint32_t laddr, int dst_rank, u64 v) {
    uint32_t raddr;
    asm volatile("mapa.shared::cluster.u32 %0, %1, %2;" : "=r"(raddr) : "r"(laddr), "r"(dst_rank));
    asm volatile("st.shared::cluster.b64 [%0], %1;" :: "r"(raddr), "l"(v) : "memory");
}
__device__ __forceinline__ void cluster_barrier() {
    asm volatile("barrier.cluster.arrive.aligned;" ::: "memory");
    asm volatile("barrier.cluster.wait.aligned;" ::: "memory");
}

__global__ __launch_bounds__(NTH, 2) __cluster_dims__(CLU, 1, 1)
void umps_id_kernel(const float* __restrict__ x,      // (256, 512, 33)
                    const float* __restrict__ core,   // (64, 33, 64)
                    const float* __restrict__ alpha,  // (64)
                    const float* __restrict__ outc,   // (64, 32)
                    float*       __restrict__ out)    // (256, 32)
{
    __shared__ u64   sU[ISL * 128];      // [iL*128 + (f-1)*4 + bp]  8192 B (warp-private rows)
    __shared__ u64   sP[256 * 9];        // [sc*9 + g] swizzled     18432 B
    __shared__ u64   sVu[40];            // [iL*5 + bp]               320 B (this CTA's 8 rows)
    __shared__ u64   sMail[2 * CLU * 32];// [(buf*8+src)*32+pos]     4096 B
    __shared__ float sX[2 * NFX * NBC];  // [buf][f-1][8 b]          2048 B

    const int tid  = threadIdx.x;
    const int rank = blockIdx.x & 7;
    const int b0   = (blockIdx.x >> 3) * NBC;   // cluster batch base
    const int g    = tid >> 5;                  // warp = local i-row 0..7
    const int l    = tid & 31;                  // lane = j-pair index (j = 2l, 2l+1)
    const uint32_t sx_base   = (uint32_t)__cvta_generic_to_shared(&sX[0]);
    const uint32_t mail_base = (uint32_t)__cvta_generic_to_shared(&sMail[0]);

    // ---- core slice (f=1..32) -> REGISTERS: cR[f-1] = core[rank*8+g][f][2l..2l+1] ----
    float2 cR[NFX];
    {
        const float* cg = core + ((size_t)(rank * ISL + g) * 33) * BOND + 2 * l;
        #pragma unroll
        for (int f = 0; f < NFX; ++f) cR[f] = *(const float2*)(cg + (f + 1) * BOND);
    }

    // ---- init this CTA's V rows: V[iL][b] = alpha[rank*8 + iL] ----
    if (tid < 32) sVu[(tid >> 2) * 5 + (tid & 3)] = pack2(alpha[rank * ISL + (tid >> 2)]);

    // ---- preload X(t=0): exactly one cp.async per thread (f=1..32, 8 b) ----
    {
        int f = tid >> 3, bl = tid & 7;
        cp_async4(sx_base + (uint32_t)(tid * 4),
                  x + ((size_t)(b0 + bl) * TLEN + 0) * 33 + (f + 1));
    }
    cp_async_commit();

    for (int t = 0; t < TLEN; ++t) {
        cp_async_wait0();
        __syncthreads();                          // B0: X(t) landed, sVu(t) visible

        const int buf = t & 1;

        // ---- prefetch X(t+1) into buf^1 ----
        if (t + 1 < TLEN) {
            int f = tid >> 3, bl = tid & 7;
            cp_async4(sx_base + (uint32_t)(((buf ^ 1) * NFX * NBC + tid) * 4),
                      x + ((size_t)(b0 + bl) * TLEN + (t + 1)) * 33 + (f + 1));
        }
        cp_async_commit();

        // ---- U-build (warp-private row g): U[g][f'][bp] = V[g][bp] * X[f'][bp] ----
        {
            const u64* sXu = (const u64*)(sX + buf * (NFX * NBC));
            u64 vb0 = sVu[g * 5 + 0], vb1 = sVu[g * 5 + 1];
            u64 vb2 = sVu[g * 5 + 2], vb3 = sVu[g * 5 + 3];
            u64* Uw = sU + g * 128;
            #pragma unroll
            for (int k = 0; k < 4; ++k) {
                int r = l + 32 * k;               // r = f'*4 + bp
                u64 vv = (r & 2) ? ((r & 1) ? vb3 : vb2) : ((r & 1) ? vb1 : vb0);
                Uw[r] = mul2(vv, sXu[r]);
            }
            __syncwarp();
        }

        // ---- GEMM over f=1..32: acc[jj*4+bp], j = 2l+jj ----
        u64 acc[8];
        #pragma unroll
        for (int q = 0; q < 8; ++q) acc[q] = 0ull;

        const ulonglong2* Ur = (const ulonglong2*)(sU + g * 128);
        #pragma unroll
        for (int f = 0; f < NFX; ++f) {
            ulonglong2 ua = Ur[2 * f];            // bp 0,1 (warp-broadcast)
            ulonglong2 ub = Ur[2 * f + 1];        // bp 2,3
            u64 c0 = pack2(cR[f].x);
            u64 c1 = pack2(cR[f].y);
            fma2(acc[0], ua.x, c0); fma2(acc[1], ua.y, c0);
            fma2(acc[2], ub.x, c0); fma2(acc[3], ub.y, c0);
            fma2(acc[4], ua.x, c1); fma2(acc[5], ua.y, c1);
            fma2(acc[6], ub.x, c1); fma2(acc[7], ub.y, c1);
        }

        // ---- store partials, conflict-free swizzle sc = q*32 + l ----
        #pragma unroll
        for (int q = 0; q < 8; ++q)
            sP[(q * 32 + l) * 9 + g] = acc[q];
        __syncthreads();                          // B2: partials visible

        // ---- reduce 8 i-rows; scatter to owner rank's mailbox ----
        {
            u64 s = sP[tid * 9];
            #pragma unroll
            for (int gg = 1; gg < ISL; ++gg) add2(s, sP[tid * 9 + gg]);
            int jp = tid & 31, q = tid >> 5;
            int jj = q >> 2, bp = q & 3;
            int j  = 2 * jp + jj;
            int own = j >> 3;
            int pos = (j & 7) * 4 + bp;
            st_cluster_u64(mail_base + (uint32_t)(((buf * CLU + rank) * 32 + pos) * 8), own, s);
        }

        cluster_barrier();                        // all scatters visible

        // ---- owner-side: sum 8 rank-partials + V_old (exact f=0 identity) ----
        if (tid < 32) {
            const u64* mb = sMail + buf * (CLU * 32);
            u64 v = mb[tid];
            #pragma unroll
            for (int r = 1; r < CLU; ++r) add2(v, mb[r * 32 + tid]);
            add2(v, sVu[(tid >> 2) * 5 + (tid & 3)]);   // V_new += V_old
            sVu[(tid >> 2) * 5 + (tid & 3)] = v;
        }
        // sVu visibility for next step via loop-top B0
    }

    // ---- gather final V rows to rank 0 (mail buf0 region is free) ----
    if (tid < 32) {
        u64 v = sVu[(tid >> 2) * 5 + (tid & 3)];
        st_cluster_u64(mail_base + (uint32_t)((rank * 32 + tid) * 8), 0, v);
    }
    cluster_barrier();

    // ---- epilogue on rank 0: out[b][o] = sum_i V[i][b] * outc[i][o] ----
    if (rank == 0) {
        const float* Vf = (const float*)sMail;   // u64 slot (i>>3)*32 + (i&7)*4 + (b>>1)
        int b = tid >> 5, o = tid & 31;
        float s = 0.f;
        #pragma unroll 8
        for (int i = 0; i < BOND; ++i) {
            float v = Vf[(((i >> 3) * 32 + (i & 7) * 4 + (b >> 1)) << 1) + (b & 1)];
            s = fmaf(v, __ldg(outc + i * OUTD + o), s);
        }
        out[(size_t)(b0 + b) * OUTD + o] = s;
    }
}

extern "C" void kernel_launch(void* const* d_in, const int* in_sizes, int n_in,
                              void* d_out, int out_size) {
    const float* x     = (const float*)d_in[0];   // (256,512,33) fp32
    const float* core  = (const float*)d_in[1];   // (64,33,64)  fp32
    const float* alpha = (const float*)d_in[2];   // (64)        fp32
    const float* outc  = (const float*)d_in[3];   // (64,32)     fp32
    float* out = (float*)d_out;                   // (256,32)    fp32

    // 32 clusters x 8 CTAs = 256 CTAs, 2 CTAs/SM (smem ~33 KB, regs ~112)
    umps_id_kernel<<<256, NTH>>>(x, core, alpha, outc, out);
}